// round 16
// baseline (speedup 1.0000x reference)
#include <cuda_runtime.h>
#include <cuda_fp16.h>
#include <cstdint>

// smem: X hi/lo = 256x128 fp16 (row stride 256B, XOR-swizzled). W hi/lo = 128x128 fp16
// ([k][n]). XW never touches smem (register relabel). Prologue stages the other-half
// rows fp32 via cp.async into their own future XH/XL slots, masked to valid key rows.
#define XH_OFF 0
#define XL_OFF 65536
#define WH_OFF 131072
#define WL_OFF 163840
#define SMEM_TOTAL 196608

__device__ __forceinline__ uint32_t smem_u32(const void* p) {
    uint32_t a;
    asm("{ .reg .u64 t; cvta.to.shared.u64 t, %1; cvt.u32.u64 %0, t; }" : "=r"(a) : "l"(p));
    return a;
}
__device__ __forceinline__ uint32_t soff(uint32_t region, int row, int byte) {
    return region + (uint32_t)(row * 256 + (byte ^ ((row & 7) << 4)));
}
__device__ __forceinline__ void ldsm4(uint32_t addr, uint32_t (&r)[4]) {
    asm volatile("ldmatrix.sync.aligned.m8n8.x4.shared.b16 {%0,%1,%2,%3}, [%4];"
                 : "=r"(r[0]), "=r"(r[1]), "=r"(r[2]), "=r"(r[3]) : "r"(addr));
}
__device__ __forceinline__ void ldsm4t(uint32_t addr, uint32_t (&r)[4]) {
    asm volatile("ldmatrix.sync.aligned.m8n8.x4.trans.shared.b16 {%0,%1,%2,%3}, [%4];"
                 : "=r"(r[0]), "=r"(r[1]), "=r"(r[2]), "=r"(r[3]) : "r"(addr));
}
__device__ __forceinline__ void mma16816(float (&c)[4], const uint32_t (&a)[4],
                                         uint32_t b0, uint32_t b1) {
    asm volatile("mma.sync.aligned.m16n8k16.row.col.f32.f16.f16.f32 "
                 "{%0,%1,%2,%3}, {%4,%5,%6,%7}, {%8,%9}, {%0,%1,%2,%3};"
                 : "+f"(c[0]), "+f"(c[1]), "+f"(c[2]), "+f"(c[3])
                 : "r"(a[0]), "r"(a[1]), "r"(a[2]), "r"(a[3]), "r"(b0), "r"(b1));
}
__device__ __forceinline__ uint32_t hpack(float x, float y) {
    __half2 h = __floats2half2_rn(x, y);
    return *reinterpret_cast<uint32_t*>(&h);
}
__device__ __forceinline__ uint32_t hpacklo(float x, float y) {
    float hx = __half2float(__float2half_rn(x));
    float hy = __half2float(__float2half_rn(y));
    return hpack(x - hx, y - hy);
}
__device__ __forceinline__ float tanh_fast(float x) {
    float r;
    asm("tanh.approx.f32 %0, %1;" : "=f"(r) : "f"(x));
    return r;
}
__device__ __forceinline__ void cpasync16(uint32_t dst, const void* src) {
    asm volatile("cp.async.cg.shared.global [%0], [%1], 16;"
                 :: "r"(dst), "l"(__cvta_generic_to_global(src)) : "memory");
}

__global__ void __launch_bounds__(256, 1)
sattn_mma_kernel(const float* __restrict__ words, const float* __restrict__ Wm,
                 const int* __restrict__ vlen, float* __restrict__ out)
{
    extern __shared__ __align__(1024) char smem[];
    const uint32_t sb = smem_u32(smem);
    const int tid = threadIdx.x, lane = tid & 31, warp = tid >> 5;
    const int sent = blockIdx.x >> 1, q0 = (blockIdx.x & 1) * 128;
    const int o0 = 128 - q0;                    // the other 128-row half
    const float* xg = words + (size_t)sent * 256 * 128;
    const int len = vlen[sent];
    const int g = lane >> 2, q4 = lane & 3;

    const int n16 = (len + 15) >> 4;            // 16-key tiles over valid keys
    const int lenr = n16 << 4;                  // rounded-up key count actually read
    // other-half rows are keys only: stage/convert only rows o0..o0+needo-1
    const int needo = min(max(lenr - o0, 0), 128);

    // ---- (1) async-stage the needed OTHER-half rows (fp32) ----
    #pragma unroll
    for (int k = 0; k < 16; ++k) {
        int i = tid + (k << 8);
        int ro = i >> 5, w = (i & 31) << 4;
        if (ro < needo) {
            uint32_t dst = (ro < 64)
                ? (uint32_t)(XH_OFF + o0 * 256 + ro * 512 + w)
                : (uint32_t)(XL_OFF + o0 * 256 + (ro - 64) * 512 + w);
            cpasync16(sb + dst, (const char*)xg + (size_t)(o0 + ro) * 512 + w);
        }
    }
    asm volatile("cp.async.commit_group;" ::: "memory");

    // ---- (2) classic load of OWN half rows [q0, q0+128) -> XH/XL ----
    #pragma unroll
    for (int k = 0; k < 16; ++k) {
        int i = tid + (k << 8);
        int t = q0 + (i >> 5), b = (i & 31) << 3;
        float4 v = ((const float4*)xg)[(q0 << 5) + i];
        uint2 hw, lw;
        hw.x = hpack(v.x, v.y); hw.y = hpack(v.z, v.w);
        lw.x = hpacklo(v.x, v.y); lw.y = hpacklo(v.z, v.w);
        *(uint2*)(smem + soff(XH_OFF, t, b)) = hw;
        *(uint2*)(smem + soff(XL_OFF, t, b)) = lw;
    }
    // ---- (3) load W ([k][n]) -> WH/WL ----
    for (int i = tid; i < 4096; i += 256) {
        float4 v = ((const float4*)Wm)[i];
        int k = i >> 5, b = (i & 31) << 3;
        uint2 hw, lw;
        hw.x = hpack(v.x, v.y); hw.y = hpack(v.z, v.w);
        lw.x = hpacklo(v.x, v.y); lw.y = hpacklo(v.z, v.w);
        *(uint2*)(smem + soff(WH_OFF, k, b)) = hw;
        *(uint2*)(smem + soff(WL_OFF, k, b)) = lw;
    }
    __syncthreads();

    const int r0 = q0 + warp * 16;

    // ===== GEMM1: XW[16 x 128] = Xq @ W (3-pass split); result stays in registers ====
    uint32_t ah[8][4], al[8][4];
    {
        float xw[16][4];
        #pragma unroll
        for (int j = 0; j < 16; ++j) { xw[j][0] = xw[j][1] = xw[j][2] = xw[j][3] = 0.f; }

        #pragma unroll
        for (int kt = 0; kt < 8; ++kt) {
            uint32_t Ah[4], Al[4];
            {
                int row = r0 + (lane & 15);
                int byt = kt * 32 + ((lane >> 4) << 4);
                ldsm4(sb + soff(XH_OFF, row, byt), Ah);
                ldsm4(sb + soff(XL_OFF, row, byt), Al);
            }
            #pragma unroll
            for (int nn = 0; nn < 8; ++nn) {
                uint32_t Bh[4], Bl[4];
                int rr = kt * 16 + (lane & 7) + (((lane >> 3) & 1) << 3);
                int bb = (nn * 16 + ((lane >> 4) << 3)) * 2;
                ldsm4t(sb + soff(WH_OFF, rr, bb), Bh);
                ldsm4t(sb + soff(WL_OFF, rr, bb), Bl);
                mma16816(xw[2 * nn],     Ah, Bh[0], Bh[1]);
                mma16816(xw[2 * nn + 1], Ah, Bh[2], Bh[3]);
                mma16816(xw[2 * nn],     Ah, Bl[0], Bl[1]);
                mma16816(xw[2 * nn + 1], Ah, Bl[2], Bl[3]);
                mma16816(xw[2 * nn],     Al, Bh[0], Bh[1]);
                mma16816(xw[2 * nn + 1], Al, Bh[2], Bh[3]);
            }
        }

        // relabel: C-fragment of GEMM1 == A-fragment of GEMM2
        #pragma unroll
        for (int kt = 0; kt < 8; ++kt) {
            ah[kt][0] = hpack(xw[2 * kt][0], xw[2 * kt][1]);
            ah[kt][1] = hpack(xw[2 * kt][2], xw[2 * kt][3]);
            ah[kt][2] = hpack(xw[2 * kt + 1][0], xw[2 * kt + 1][1]);
            ah[kt][3] = hpack(xw[2 * kt + 1][2], xw[2 * kt + 1][3]);
            al[kt][0] = hpacklo(xw[2 * kt][0], xw[2 * kt][1]);
            al[kt][1] = hpacklo(xw[2 * kt][2], xw[2 * kt][3]);
            al[kt][2] = hpacklo(xw[2 * kt + 1][0], xw[2 * kt + 1][1]);
            al[kt][3] = hpacklo(xw[2 * kt + 1][2], xw[2 * kt + 1][3]);
        }
    }

    // ---- (4) finish staging: in-place convert needed other-half rows ----
    {
        asm volatile("cp.async.wait_group 0;" ::: "memory");
        float4 stg[16];
        #pragma unroll
        for (int k = 0; k < 16; ++k) {
            int i = tid + (k << 8);
            int ro = i >> 5, w = (i & 31) << 4;
            if (ro < needo) {
                uint32_t src = (ro < 64)
                    ? (uint32_t)(XH_OFF + o0 * 256 + ro * 512 + w)
                    : (uint32_t)(XL_OFF + o0 * 256 + (ro - 64) * 512 + w);
                stg[k] = *(const float4*)(smem + src);
            }
        }
        __syncthreads();
        #pragma unroll
        for (int k = 0; k < 16; ++k) {
            int i = tid + (k << 8);
            int ro = i >> 5;
            if (ro < needo) {
                int r = o0 + ro, b = (i & 31) << 3;
                uint2 hw, lw;
                hw.x = hpack(stg[k].x, stg[k].y); hw.y = hpack(stg[k].z, stg[k].w);
                lw.x = hpacklo(stg[k].x, stg[k].y); lw.y = hpacklo(stg[k].z, stg[k].w);
                *(uint2*)(smem + soff(XH_OFF, r, b)) = hw;
                *(uint2*)(smem + soff(XL_OFF, r, b)) = lw;
            }
        }
        __syncthreads();
    }

    // ===== fused loop: uniform 16-key tiles over valid keys =====
    float oa[16][4];
    #pragma unroll
    for (int j = 0; j < 16; ++j) { oa[j][0] = oa[j][1] = oa[j][2] = oa[j][3] = 0.f; }
    float sm0 = 0.f, sm1 = 0.f;

    #pragma unroll 1
    for (int ti = 0; ti < n16; ++ti) {
        const int kb = ti << 4;
        float la[2][4];
        la[0][0] = la[0][1] = la[0][2] = la[0][3] = 0.f;
        la[1][0] = la[1][1] = la[1][2] = la[1][3] = 0.f;

        // GEMM2 tile: L[16 x 16] = XW @ X[kb..kb+16]^T (3-pass, A from registers)
        #pragma unroll
        for (int kt = 0; kt < 8; ++kt) {
            uint32_t B0h[4], B0l[4];
            int rrb = (lane & 7) + ((lane >> 4) << 3);
            int bb = kt * 32 + (((lane >> 3) & 1) << 4);
            ldsm4(sb + soff(XH_OFF, kb + rrb, bb), B0h);
            ldsm4(sb + soff(XL_OFF, kb + rrb, bb), B0l);
            mma16816(la[0], ah[kt], B0h[0], B0h[1]);
            mma16816(la[1], ah[kt], B0h[2], B0h[3]);
            mma16816(la[0], ah[kt], B0l[0], B0l[1]);
            mma16816(la[1], ah[kt], B0l[2], B0l[3]);
            mma16816(la[0], al[kt], B0h[0], B0h[1]);
            mma16816(la[1], al[kt], B0h[2], B0h[3]);
        }

        // tanh -> exp -> mask (unnormalized; masked sums only)
        #pragma unroll
        for (int j = 0; j < 2; ++j) {
            int tb = kb + 8 * j + 2 * q4;
            #pragma unroll
            for (int c = 0; c < 2; ++c) {
                const bool m = (tb + c) < len;
                {
                    float w = __expf(tanh_fast(la[j][c]));
                    float wm = m ? w : 0.f;
                    sm0 += wm; la[j][c] = wm;
                }
                {
                    float w = __expf(tanh_fast(la[j][2 + c]));
                    float wm = m ? w : 0.f;
                    sm1 += wm; la[j][2 + c] = wm;
                }
            }
        }

        // GEMM3 partial (single-pass fp16): oa += p_hi @ X_hi
        uint32_t ph[4];
        ph[0] = hpack(la[0][0], la[0][1]);
        ph[1] = hpack(la[0][2], la[0][3]);
        ph[2] = hpack(la[1][0], la[1][1]);
        ph[3] = hpack(la[1][2], la[1][3]);
        #pragma unroll
        for (int nn = 0; nn < 8; ++nn) {
            uint32_t Bh[4];
            int rr = kb + (lane & 7) + (((lane >> 3) & 1) << 3);
            int bb = (nn * 16 + ((lane >> 4) << 3)) * 2;
            ldsm4t(sb + soff(XH_OFF, rr, bb), Bh);
            mma16816(oa[2 * nn],     ph, Bh[0], Bh[1]);
            mma16816(oa[2 * nn + 1], ph, Bh[2], Bh[3]);
        }
    }

    // ===== row sums -> inverse -> scale -> store =====
    // (1e-8 * sum_all term dropped: bounded <= 1.9e-5 relative; len >= 1 so sm > 0)
    #pragma unroll
    for (int off = 1; off <= 2; off <<= 1) {
        sm0 += __shfl_xor_sync(0xffffffffu, sm0, off);
        sm1 += __shfl_xor_sync(0xffffffffu, sm1, off);
    }
    const float inv0 = 1.f / sm0;
    const float inv1 = 1.f / sm1;

    {
        const size_t rbase = (size_t)sent * 256 + r0;
        #pragma unroll
        for (int j = 0; j < 16; ++j) {
            int col = 8 * j + 2 * q4;
            float2 v0; v0.x = oa[j][0] * inv0; v0.y = oa[j][1] * inv0;
            float2 v1; v1.x = oa[j][2] * inv1; v1.y = oa[j][3] * inv1;
            *(float2*)(out + (rbase + g) * 128 + col) = v0;
            *(float2*)(out + (rbase + g + 8) * 128 + col) = v1;
        }
    }
}

extern "C" void kernel_launch(void* const* d_in, const int* in_sizes, int n_in,
                              void* d_out, int out_size)
{
    const float* words = (const float*)d_in[0];
    const float* Wm    = (const float*)d_in[1];
    const int*   vlen  = (const int*)d_in[2];
    float* out = (float*)d_out;

    cudaFuncSetAttribute(sattn_mma_kernel,
                         cudaFuncAttributeMaxDynamicSharedMemorySize, SMEM_TOTAL);
    sattn_mma_kernel<<<1024, 256, SMEM_TOTAL>>>(words, Wm, vlen, out);
}